// round 8
// baseline (speedup 1.0000x reference)
#include <cuda_runtime.h>

#define N_ATOMS 100000
#define N_PAIRS 3200000
#define NT4     (N_PAIRS / 4)   // 800000 thread-work-items, exact
#define ZMAX    96
#define NBLK    296              // two persistent CTAs per SM
#define NTHR    1024
#define SMEM_BYTES (N_ATOMS + ZMAX * 4 + 48)   // z8 table + zpow LUT + params

// Scratch (no allocation allowed)
__device__ __align__(16) unsigned char g_z8[N_ATOMS];  // Z in [1,95), 100KB
__device__ float  g_zpow[ZMAX];                        // z^|a_exponent| LUT
__device__ float4 g_params4[3];                        // [0]=c  [1]=e  [2]={inv_a,K,-,-}

__global__ void __launch_bounds__(256) prep_kernel(
    const int* __restrict__ Z,
    const float* __restrict__ a_coef, const float* __restrict__ a_exp,
    const float* __restrict__ phi_c,  const float* __restrict__ phi_e,
    const float* __restrict__ ke,     const float* __restrict__ d2A,
    const float* __restrict__ e2m,
    float* __restrict__ out)
{
    int n = blockIdx.x * blockDim.x + threadIdx.x;
    if (n == 0) {
        float a0 = fabsf(phi_c[0]), a1 = fabsf(phi_c[1]),
              a2 = fabsf(phi_c[2]), a3 = fabsf(phi_c[3]);
        float inv_s = 1.0f / (a0 + a1 + a2 + a3);
        g_params4[0] = make_float4(a0 * inv_s, a1 * inv_s, a2 * inv_s, a3 * inv_s);
        g_params4[1] = make_float4(fabsf(phi_e[0]), fabsf(phi_e[1]),
                                   fabsf(phi_e[2]), fabsf(phi_e[3]));
        g_params4[2] = make_float4(1.0f / fabsf(a_coef[0]),
                                   ke[0] * e2m[0] / d2A[0], 0.0f, 0.0f);
    }
    if (n < ZMAX) {
        g_zpow[n] = __powf((float)n, fabsf(a_exp[0]));
    }
    if (n < N_ATOMS) {
        g_z8[n] = (unsigned char)Z[n];
        out[n] = 0.0f;                     // d_out poisoned -> zero it
    }
}

__global__ void __launch_bounds__(NTHR, 2) pair_kernel(
    const float4* __restrict__ dist, const float4* __restrict__ cut,
    const int4*  __restrict__ idx_i, const int4*  __restrict__ idx_j,
    float* __restrict__ out)
{
    extern __shared__ unsigned char smem[];
    unsigned char* s_z8   = smem;
    float*         s_zpow = (float*)(smem + N_ATOMS);           // N_ATOMS % 16 == 0
    float*         s_par  = (float*)(smem + N_ATOMS + ZMAX * 4); // 12 floats

    // Stage 100KB Z table + LUT + params into smem (L2-resident source)
    {
        const int4* src = (const int4*)g_z8;
        int4*       dst = (int4*)s_z8;
        #pragma unroll 4
        for (int i = threadIdx.x; i < N_ATOMS / 16; i += NTHR) dst[i] = src[i];
        if (threadIdx.x < ZMAX) s_zpow[threadIdx.x] = g_zpow[threadIdx.x];
        if (threadIdx.x < 12)   s_par[threadIdx.x]  = ((const float*)g_params4)[threadIdx.x];
    }
    __syncthreads();

    for (int t = blockIdx.x * NTHR + threadIdx.x; t < NT4; t += NBLK * NTHR) {
        int4   si = __ldg(idx_i + t);
        int4   sj = __ldg(idx_j + t);
        float4 d  = __ldg(dist  + t);
        float4 ct = __ldg(cut   + t);

        // smem gathers (zi nearly uniform -> broadcast; zj random -> low conflict)
        int zi0 = s_z8[si.x], zi1 = s_z8[si.y], zi2 = s_z8[si.z], zi3 = s_z8[si.w];
        int zj0 = s_z8[sj.x], zj1 = s_z8[sj.y], zj2 = s_z8[sj.z], zj3 = s_z8[sj.w];

        // params from smem (broadcast LDS, keeps register count <= 32)
        float inv_a = s_par[8], K = s_par[9];
        float a0 = d.x * (s_zpow[zi0] + s_zpow[zj0]) * inv_a;
        float a1 = d.y * (s_zpow[zi1] + s_zpow[zj1]) * inv_a;
        float a2 = d.z * (s_zpow[zi2] + s_zpow[zj2]) * inv_a;
        float a3 = d.w * (s_zpow[zi3] + s_zpow[zj3]) * inv_a;

        float p0 = 0.f, p1 = 0.f, p2 = 0.f, p3 = 0.f;
        #pragma unroll
        for (int k = 0; k < 4; k++) {
            float ck = s_par[k], ek = s_par[4 + k];
            p0 += ck * __expf(-ek * a0);
            p1 += ck * __expf(-ek * a1);
            p2 += ck * __expf(-ek * a2);
            p3 += ck * __expf(-ek * a3);
        }

        float v0 = K * (float)(zi0 * zj0) * p0 * ct.x * __fdividef(1.0f, d.x);
        float v1 = K * (float)(zi1 * zj1) * p1 * ct.y * __fdividef(1.0f, d.y);
        float v2 = K * (float)(zi2 * zj2) * p2 * ct.z * __fdividef(1.0f, d.z);
        float v3 = K * (float)(zi3 * zj3) * p3 * ct.w * __fdividef(1.0f, d.w);

        // Thread-local segmented accumulation; fire-and-forget atomics at
        // boundaries (idx_i sorted, ~32 pairs/segment).
        int   seg = si.x;
        float acc = v0;
        #define ZSTEP(S, V) \
            if ((S) == seg) acc += (V); \
            else { atomicAdd(&out[seg], acc); seg = (S); acc = (V); }
        ZSTEP(si.y, v1) ZSTEP(si.z, v2) ZSTEP(si.w, v3)
        #undef ZSTEP
        atomicAdd(&out[seg], acc);
    }
}

extern "C" void kernel_launch(void* const* d_in, const int* in_sizes, int n_in,
                              void* d_out, int out_size)
{
    const int*   Z    = (const int*)  d_in[0];
    const float* dist = (const float*)d_in[1];
    const float* cutv = (const float*)d_in[2];
    const int*   ii   = (const int*)  d_in[3];
    const int*   jj   = (const int*)  d_in[4];
    const float* ac   = (const float*)d_in[5];
    const float* ae   = (const float*)d_in[6];
    const float* pc   = (const float*)d_in[7];
    const float* pe   = (const float*)d_in[8];
    const float* ke   = (const float*)d_in[9];
    const float* d2A  = (const float*)d_in[10];
    const float* e2m  = (const float*)d_in[11];
    float* out = (float*)d_out;

    cudaFuncSetAttribute(pair_kernel,
                         cudaFuncAttributeMaxDynamicSharedMemorySize, SMEM_BYTES);

    prep_kernel<<<(N_ATOMS + 255) / 256, 256>>>(Z, ac, ae, pc, pe, ke, d2A, e2m, out);
    pair_kernel<<<NBLK, NTHR, SMEM_BYTES>>>(
        (const float4*)dist, (const float4*)cutv,
        (const int4*)ii, (const int4*)jj, out);
}

// round 9
// speedup vs baseline: 1.1332x; 1.1332x over previous
#include <cuda_runtime.h>

#define N_ATOMS 100000
#define N_PAIRS 3200000
#define NT8     (N_PAIRS / 8)   // 400000 thread-work-items, exact
#define ZMAX    96
#define NBLK    148
#define NTHR    768
#define SMEM_BYTES (N_ATOMS + ZMAX * 4)   // 100384 bytes dynamic smem

// Scratch (no allocation allowed)
__device__ __align__(16) unsigned char g_z8[N_ATOMS];  // Z in [1,95), 100KB
__device__ float  g_zpow[ZMAX];                        // z^|a_exponent| LUT
__device__ float4 g_params4[3];                        // [0]=c  [1]=e  [2]={inv_a,K,-,-}

__global__ void __launch_bounds__(256) prep_kernel(
    const int* __restrict__ Z,
    const float* __restrict__ a_coef, const float* __restrict__ a_exp,
    const float* __restrict__ phi_c,  const float* __restrict__ phi_e,
    const float* __restrict__ ke,     const float* __restrict__ d2A,
    const float* __restrict__ e2m,
    float* __restrict__ out)
{
    int n = blockIdx.x * blockDim.x + threadIdx.x;
    if (n == 0) {
        float a0 = fabsf(phi_c[0]), a1 = fabsf(phi_c[1]),
              a2 = fabsf(phi_c[2]), a3 = fabsf(phi_c[3]);
        float inv_s = 1.0f / (a0 + a1 + a2 + a3);
        g_params4[0] = make_float4(a0 * inv_s, a1 * inv_s, a2 * inv_s, a3 * inv_s);
        g_params4[1] = make_float4(fabsf(phi_e[0]), fabsf(phi_e[1]),
                                   fabsf(phi_e[2]), fabsf(phi_e[3]));
        g_params4[2] = make_float4(1.0f / fabsf(a_coef[0]),
                                   ke[0] * e2m[0] / d2A[0], 0.0f, 0.0f);
    }
    if (n < ZMAX) {
        g_zpow[n] = __powf((float)n, fabsf(a_exp[0]));
    }
    if (n < N_ATOMS) {
        g_z8[n] = (unsigned char)Z[n];
        out[n] = 0.0f;                     // d_out poisoned -> zero it
    }
}

struct Tile {
    int4   si0, si1, sj0, sj1;
    float4 d0,  d1,  ct0, ct1;
};

__device__ __forceinline__ void load_tile(
    Tile& T, int t,
    const int4* __restrict__ idx_i, const int4* __restrict__ idx_j,
    const float4* __restrict__ dist, const float4* __restrict__ cut)
{
    T.si0 = __ldg(idx_i + 2 * t);  T.si1 = __ldg(idx_i + 2 * t + 1);
    T.sj0 = __ldg(idx_j + 2 * t);  T.sj1 = __ldg(idx_j + 2 * t + 1);
    T.d0  = __ldg(dist  + 2 * t);  T.d1  = __ldg(dist  + 2 * t + 1);
    T.ct0 = __ldg(cut   + 2 * t);  T.ct1 = __ldg(cut   + 2 * t + 1);
}

__device__ __forceinline__ float pair_val(
    float d, float ct, int zi, int zj, const float* __restrict__ s_zpow,
    float4 C, float4 E, float inv_a, float K)
{
    float arg = d * (s_zpow[zi] + s_zpow[zj]) * inv_a;
    float phi = C.x * __expf(-E.x * arg)
              + C.y * __expf(-E.y * arg)
              + C.z * __expf(-E.z * arg)
              + C.w * __expf(-E.w * arg);
    return K * (float)(zi * zj) * phi * ct * __fdividef(1.0f, d);
}

__device__ __forceinline__ void compute_tile(
    const Tile& T, const unsigned char* __restrict__ s_z8,
    const float* __restrict__ s_zpow,
    float4 C, float4 E, float inv_a, float K, float* __restrict__ out)
{
    int zi0 = s_z8[T.si0.x], zi1 = s_z8[T.si0.y], zi2 = s_z8[T.si0.z], zi3 = s_z8[T.si0.w];
    int zj0 = s_z8[T.sj0.x], zj1 = s_z8[T.sj0.y], zj2 = s_z8[T.sj0.z], zj3 = s_z8[T.sj0.w];
    int zi4 = s_z8[T.si1.x], zi5 = s_z8[T.si1.y], zi6 = s_z8[T.si1.z], zi7 = s_z8[T.si1.w];
    int zj4 = s_z8[T.sj1.x], zj5 = s_z8[T.sj1.y], zj6 = s_z8[T.sj1.z], zj7 = s_z8[T.sj1.w];

    float v0 = pair_val(T.d0.x, T.ct0.x, zi0, zj0, s_zpow, C, E, inv_a, K);
    float v1 = pair_val(T.d0.y, T.ct0.y, zi1, zj1, s_zpow, C, E, inv_a, K);
    float v2 = pair_val(T.d0.z, T.ct0.z, zi2, zj2, s_zpow, C, E, inv_a, K);
    float v3 = pair_val(T.d0.w, T.ct0.w, zi3, zj3, s_zpow, C, E, inv_a, K);
    float v4 = pair_val(T.d1.x, T.ct1.x, zi4, zj4, s_zpow, C, E, inv_a, K);
    float v5 = pair_val(T.d1.y, T.ct1.y, zi5, zj5, s_zpow, C, E, inv_a, K);
    float v6 = pair_val(T.d1.z, T.ct1.z, zi6, zj6, s_zpow, C, E, inv_a, K);
    float v7 = pair_val(T.d1.w, T.ct1.w, zi7, zj7, s_zpow, C, E, inv_a, K);

    int   seg = T.si0.x;
    float acc = v0;
    #define ZSTEP(S, V) \
        if ((S) == seg) acc += (V); \
        else { atomicAdd(&out[seg], acc); seg = (S); acc = (V); }
    ZSTEP(T.si0.y, v1) ZSTEP(T.si0.z, v2) ZSTEP(T.si0.w, v3)
    ZSTEP(T.si1.x, v4) ZSTEP(T.si1.y, v5) ZSTEP(T.si1.z, v6) ZSTEP(T.si1.w, v7)
    #undef ZSTEP
    atomicAdd(&out[seg], acc);
}

__global__ void __launch_bounds__(NTHR, 1) pair_kernel(
    const float4* __restrict__ dist, const float4* __restrict__ cut,
    const int4*  __restrict__ idx_i, const int4*  __restrict__ idx_j,
    float* __restrict__ out)
{
    extern __shared__ unsigned char smem[];
    unsigned char* s_z8   = smem;
    float*         s_zpow = (float*)(smem + N_ATOMS);   // N_ATOMS % 16 == 0

    // Stage 100KB Z table into smem (L2-resident source)
    {
        const int4* src = (const int4*)g_z8;
        int4*       dst = (int4*)s_z8;
        #pragma unroll 4
        for (int i = threadIdx.x; i < N_ATOMS / 16; i += NTHR) dst[i] = src[i];
        if (threadIdx.x < ZMAX) s_zpow[threadIdx.x] = g_zpow[threadIdx.x];
    }
    __syncthreads();

    float4 C  = g_params4[0];
    float4 E  = g_params4[1];
    float4 P2 = g_params4[2];
    float inv_a = P2.x, K = P2.y;

    const int stride = NBLK * NTHR;
    int t = blockIdx.x * NTHR + threadIdx.x;

    Tile cur, nxt;
    bool valid = (t < NT8);
    if (valid) load_tile(cur, t, idx_i, idx_j, dist, cut);

    #pragma unroll 2
    while (valid) {
        int tn = t + stride;
        bool nvalid = (tn < NT8);
        if (nvalid) load_tile(nxt, tn, idx_i, idx_j, dist, cut);  // in flight during compute
        compute_tile(cur, s_z8, s_zpow, C, E, inv_a, K, out);
        cur = nxt;
        t = tn;
        valid = nvalid;
    }
}

extern "C" void kernel_launch(void* const* d_in, const int* in_sizes, int n_in,
                              void* d_out, int out_size)
{
    const int*   Z    = (const int*)  d_in[0];
    const float* dist = (const float*)d_in[1];
    const float* cutv = (const float*)d_in[2];
    const int*   ii   = (const int*)  d_in[3];
    const int*   jj   = (const int*)  d_in[4];
    const float* ac   = (const float*)d_in[5];
    const float* ae   = (const float*)d_in[6];
    const float* pc   = (const float*)d_in[7];
    const float* pe   = (const float*)d_in[8];
    const float* ke   = (const float*)d_in[9];
    const float* d2A  = (const float*)d_in[10];
    const float* e2m  = (const float*)d_in[11];
    float* out = (float*)d_out;

    cudaFuncSetAttribute(pair_kernel,
                         cudaFuncAttributeMaxDynamicSharedMemorySize, SMEM_BYTES);

    prep_kernel<<<(N_ATOMS + 255) / 256, 256>>>(Z, ac, ae, pc, pe, ke, d2A, e2m, out);
    pair_kernel<<<NBLK, NTHR, SMEM_BYTES>>>(
        (const float4*)dist, (const float4*)cutv,
        (const int4*)ii, (const int4*)jj, out);
}